// round 16
// baseline (speedup 1.0000x reference)
#include <cuda_runtime.h>
#include <cuda_fp16.h>
#include <cstdint>

#define NN_CAP 100000
#define EE_CAP 1600000
#define SCAN_B 1024

// ---------------- scratch (device globals) ----------------
__device__ int    g_is64;
__device__ int    g_cnt[NN_CAP];
__device__ int    g_off[NN_CAP + 1];
__device__ int    g_cur[NN_CAP];
__device__ int    g_bsum[(NN_CAP + SCAN_B - 1) / SCAN_B];
__device__ int    g_bpre[(NN_CAP + SCAN_B - 1) / SCAN_B];
__device__ int    g_ssrc[EE_CAP];
__device__ __half g_xl1h[(size_t)NN_CAP * 128];
__device__ __half g_xr1h[(size_t)NN_CAP * 128];
__device__ __half g_xl2h[(size_t)NN_CAP * 64];
__device__ __half g_xr2h[(size_t)NN_CAP * 64];
__device__ __half g_x16[(size_t)NN_CAP * 128];
__device__ __half g_h16[(size_t)NN_CAP * 128];
__device__ __half g_w1l16[16384], g_w1r16[16384];
__device__ __half g_w2l16[8192],  g_w2r16[8192];

// ---------------- helpers ----------------
__device__ __forceinline__ uint32_t smem_u32(const void* p) {
    uint32_t a;
    asm("{ .reg .u64 t; cvta.to.shared.u64 t, %1; cvt.u32.u64 %0, t; }" : "=r"(a) : "l"(p));
    return a;
}
__device__ __forceinline__ void ldsm_x4(uint32_t& r0, uint32_t& r1, uint32_t& r2, uint32_t& r3,
                                        uint32_t addr) {
    asm volatile("ldmatrix.sync.aligned.m8n8.x4.shared.b16 {%0,%1,%2,%3}, [%4];"
                 : "=r"(r0), "=r"(r1), "=r"(r2), "=r"(r3) : "r"(addr));
}
__device__ __forceinline__ void mma16816f(float* c, const uint32_t* a, const uint32_t* b) {
    asm volatile(
        "mma.sync.aligned.m16n8k16.row.col.f32.f16.f16.f32 "
        "{%0,%1,%2,%3}, {%4,%5,%6,%7}, {%8,%9}, {%0,%1,%2,%3};"
        : "+f"(c[0]), "+f"(c[1]), "+f"(c[2]), "+f"(c[3])
        : "r"(a[0]), "r"(a[1]), "r"(a[2]), "r"(a[3]), "r"(b[0]), "r"(b[1]));
}
__device__ __forceinline__ float4 h4_to_f4(uint2 u) {
    float2 a = __half22float2(*(__half2*)&u.x);
    float2 b = __half22float2(*(__half2*)&u.y);
    return make_float4(a.x, a.y, b.x, b.y);
}
__device__ __forceinline__ float score4_h2(uint2 xl, uint2 xr, uint2 at) {
    const __half2 k = __float2half2_rn(0.2f);
    __half2 e0 = __hadd2(*(__half2*)&xl.x, *(__half2*)&xr.x);
    __half2 e1 = __hadd2(*(__half2*)&xl.y, *(__half2*)&xr.y);
    __half2 l0 = __hmax2(e0, __hmul2(e0, k));
    __half2 l1 = __hmax2(e1, __hmul2(e1, k));
    __half2 p  = __hmul2(l0, *(__half2*)&at.x);
    p = __hfma2(l1, *(__half2*)&at.y, p);
    float2 f = __half22float2(p);
    return f.x + f.y;
}
__device__ __forceinline__ int edge_dst(const int* __restrict__ ei, int e, int E, int is64) {
    return is64 ? ei[2 * (E + e)] : ei[E + e];
}
__device__ __forceinline__ int edge_src(const int* __restrict__ ei, int e, int E, int is64) {
    return is64 ? ei[2 * e] : ei[e];
}

// ---------------- init: zero counts + dtype detect (block 0) ----------------
__global__ void k_init(const int* __restrict__ ei, int E, int N) {
    int t = blockIdx.x * blockDim.x + threadIdx.x;
    if (t < N) g_cnt[t] = 0;
    if (blockIdx.x == 0) {
        __shared__ int nz;
        if (threadIdx.x == 0) nz = 0;
        __syncthreads();
        int cnt = E < 4096 ? E : 4096;
        for (int i = threadIdx.x; i < cnt; i += blockDim.x)
            if (ei[2 * i + 1] != 0) nz = 1;
        __syncthreads();
        if (threadIdx.x == 0) g_is64 = (nz == 0) ? 1 : 0;
    }
}

// ---------------- CSR build ----------------
__global__ void k_hist(const int* __restrict__ ei, int E) {
    int e = blockIdx.x * blockDim.x + threadIdx.x;
    if (e >= E) return;
    atomicAdd(&g_cnt[edge_dst(ei, e, E, g_is64)], 1);
}
__global__ void k_scan1(int N) {
    __shared__ int wsum[32];
    const int tid = threadIdx.x;
    const int i = blockIdx.x * SCAN_B + tid;
    const int lane = tid & 31, wid = tid >> 5;
    int v = (i < N) ? g_cnt[i] : 0;
    int incl = v;
#pragma unroll
    for (int o = 1; o < 32; o <<= 1) {
        int t = __shfl_up_sync(0xFFFFFFFFu, incl, o);
        if (lane >= o) incl += t;
    }
    if (lane == 31) wsum[wid] = incl;
    __syncthreads();
    if (wid == 0) {
        int w = wsum[lane];
        int wi = w;
#pragma unroll
        for (int o = 1; o < 32; o <<= 1) {
            int t = __shfl_up_sync(0xFFFFFFFFu, wi, o);
            if (lane >= o) wi += t;
        }
        wsum[lane] = wi - w;
        if (lane == 31) g_bsum[blockIdx.x] = wi;
    }
    __syncthreads();
    if (i < N) g_off[i] = incl - v + wsum[wid];
}
__global__ void k_scan2(int NB, int N) {
    const int lane = threadIdx.x & 31, wid = threadIdx.x >> 5;
    __shared__ int wsum[4];
    int v = (threadIdx.x < NB) ? g_bsum[threadIdx.x] : 0;
    int incl = v;
#pragma unroll
    for (int o = 1; o < 32; o <<= 1) {
        int t = __shfl_up_sync(0xFFFFFFFFu, incl, o);
        if (lane >= o) incl += t;
    }
    if (lane == 31) wsum[wid] = incl;
    __syncthreads();
    int pre = 0;
    for (int w = 0; w < wid; w++) pre += wsum[w];
    if (threadIdx.x < NB) g_bpre[threadIdx.x] = pre + incl - v;
    if (threadIdx.x == 127) g_off[N] = pre + incl;
}
__global__ void k_scan3(int N) {
    int t = blockIdx.x * blockDim.x + threadIdx.x;
    if (t >= N) return;
    int o = g_off[t] + g_bpre[t >> 10];
    g_off[t] = o;
    g_cur[t] = o;
}
__global__ void k_scatter(const int* __restrict__ ei, int E) {
    int e = blockIdx.x * blockDim.x + threadIdx.x;
    if (e >= E) return;
    int is64 = g_is64;
    int s = edge_src(ei, e, E, is64), d = edge_dst(ei, e, E, is64);
    int pos = atomicAdd(&g_cur[d], 1);
    g_ssrc[pos] = s;
}

// ---------------- weight prep: transpose to [NOUT][128] fp16 ----------------
__global__ void k_wprep(const float* __restrict__ W1l, const float* __restrict__ W1r,
                        const float* __restrict__ W2l, const float* __restrict__ W2r) {
    int t = blockIdx.x * blockDim.x + threadIdx.x;
    const float* W; __half* o; int NOUT, idx;
    if      (t < 16384)  { W = W1l; o = g_w1l16; NOUT = 128; idx = t; }
    else if (t < 32768)  { W = W1r; o = g_w1r16; NOUT = 128; idx = t - 16384; }
    else if (t < 40960)  { W = W2l; o = g_w2l16; NOUT = 64;  idx = t - 32768; }
    else if (t < 49152)  { W = W2r; o = g_w2r16; NOUT = 64;  idx = t - 40960; }
    else return;
    int n = idx >> 7, k = idx & 127;
    o[idx] = __float2half_rn(W[k * NOUT + n]);
}

// ---------------- X prep: fp32 -> fp16 ----------------
__global__ void k_xprep(const float* __restrict__ X, int total4) {
    int t = blockIdx.x * blockDim.x + threadIdx.x;
    if (t >= total4) return;
    float4 v = *(const float4*)&X[t * 4];
    uint2 h;
    *(__half2*)&h.x = __floats2half2_rn(v.x, v.y);
    *(__half2*)&h.y = __floats2half2_rn(v.z, v.w);
    *(uint2*)&g_x16[t * 4] = h;
}

// ---------------- single-pass fp16 mma.sync GEMM pair (NTILE=64) ----------------
template <int NOUT, int NTILE>
__global__ void __launch_bounds__(256, 2) k_gemm_mma(
    const __half* __restrict__ Xh,
    const __half* __restrict__ Wl, const __half* __restrict__ Wr,
    const float* __restrict__ bl, const float* __restrict__ br,
    __half* __restrict__ Ylh, __half* __restrict__ Yrh, int nrows)
{
    constexpr int PITCH = 136;
    constexpr int ABYTES = 128 * PITCH * 2;      // 34816
    constexpr int BBYTES = NTILE * PITCH * 2;    // 17408 for NTILE=64
    constexpr int WN = NTILE / 2;                // 32
    constexpr int NFRAG = WN / 8;                // 4

    extern __shared__ char sm[];
    __half* At = (__half*)sm;
    __half* Bt = (__half*)(sm + ABYTES);

    const int tid = threadIdx.x, wid = tid >> 5, lane = tid & 31;
    const int wm = wid & 3, wn = wid >> 2;
    const int base = blockIdx.x * 128;
    const int cbase = blockIdx.y * NTILE;

    for (int c = tid; c < 2048; c += 256) {
        int row = c >> 4, col8 = (c & 15) << 3;
        int gr = base + row;
        uint4 v = make_uint4(0u, 0u, 0u, 0u);
        if (gr < nrows) v = *(const uint4*)&Xh[(size_t)gr * 128 + col8];
        *(uint4*)&At[row * PITCH + col8] = v;
    }
    const __half* wsrc[2] = {Wl, Wr};
#pragma unroll
    for (int w = 0; w < 2; w++) {
        __half* dst = Bt + w * (NTILE * PITCH);
        const __half* src = wsrc[w] + (size_t)cbase * 128;
        for (int c = tid; c < NTILE * 16; c += 256) {
            int row = c >> 4, col8 = (c & 15) << 3;
            *(uint4*)&dst[row * PITCH + col8] = *(const uint4*)&src[row * 128 + col8];
        }
    }
    __syncthreads();

    const int quad = lane >> 3, r = lane & 7;
    const int a_row_off = (quad & 1) * 8 + r, a_col_off = (quad >> 1) * 8;
    const int b_row_off = (quad >> 1) * 8 + r, b_col_off = (quad & 1) * 8;

    const uint32_t a_u = smem_u32(At), b_u = smem_u32(Bt);

    float acc[2][2][NFRAG][4];
#pragma unroll
    for (int o = 0; o < 2; o++)
#pragma unroll
        for (int mf = 0; mf < 2; mf++)
#pragma unroll
            for (int nf = 0; nf < NFRAG; nf++)
                acc[o][mf][nf][0] = acc[o][mf][nf][1] = acc[o][mf][nf][2] = acc[o][mf][nf][3] = 0.f;

#pragma unroll
    for (int ks = 0; ks < 8; ks++) {
        uint32_t af[2][4];
#pragma unroll
        for (int mf = 0; mf < 2; mf++) {
            uint32_t off = ((wm * 32 + mf * 16 + a_row_off) * PITCH + ks * 16 + a_col_off) * 2;
            ldsm_x4(af[mf][0], af[mf][1], af[mf][2], af[mf][3], a_u + off);
        }
#pragma unroll
        for (int out = 0; out < 2; out++) {
            uint32_t bf[NFRAG][2];
            uint32_t boff = ((wn * WN + b_row_off) * PITCH + ks * 16 + b_col_off) * 2;
#pragma unroll
            for (int nfp = 0; nfp < NFRAG / 2; nfp++) {
                uint32_t d0, d1, d2, d3;
                ldsm_x4(d0, d1, d2, d3,
                        b_u + (uint32_t)out * BBYTES + boff + nfp * 16 * PITCH * 2);
                bf[2 * nfp][0] = d0; bf[2 * nfp][1] = d1;
                bf[2 * nfp + 1][0] = d2; bf[2 * nfp + 1][1] = d3;
            }
#pragma unroll
            for (int mf = 0; mf < 2; mf++)
#pragma unroll
                for (int nf = 0; nf < NFRAG; nf++)
                    mma16816f(acc[out][mf][nf], af[mf], bf[nf]);
        }
    }

#pragma unroll
    for (int out = 0; out < 2; out++) {
        const float* bias = out ? br : bl;
        __half* Y = out ? Yrh : Ylh;
#pragma unroll
        for (int mf = 0; mf < 2; mf++) {
            int row0 = base + wm * 32 + mf * 16 + (lane >> 2);
#pragma unroll
            for (int nf = 0; nf < NFRAG; nf++) {
                int col = cbase + wn * WN + nf * 8 + (lane & 3) * 2;
                float b0 = __ldg(&bias[col]), b1 = __ldg(&bias[col + 1]);
                if (row0 < nrows)
                    *(__half2*)&Y[(size_t)row0 * NOUT + col] =
                        __floats2half2_rn(acc[out][mf][nf][0] + b0, acc[out][mf][nf][1] + b1);
                if (row0 + 8 < nrows)
                    *(__half2*)&Y[(size_t)(row0 + 8) * NOUT + col] =
                        __floats2half2_rn(acc[out][mf][nf][2] + b0, acc[out][mf][nf][3] + b1);
            }
        }
    }
}

// ---------------- layer 1 attention: shuffle-broadcast indices ----------
__global__ void k_attn1(const float* __restrict__ att, const float* __restrict__ bias, int N) {
    int node = blockIdx.x * 8 + (threadIdx.x >> 5);
    int lane = threadIdx.x & 31;
    if (node >= N) return;
    const int d = node;
    const __half* XL = g_xl1h;
    const unsigned FULL = 0xFFFFFFFFu;

    uint2 xr = *(const uint2*)&g_xr1h[(size_t)d * 128 + lane * 4];
    float4 atf = *(const float4*)&att[lane * 4];
    uint2 at;
    *(__half2*)&at.x = __floats2half2_rn(atf.x, atf.y);
    *(__half2*)&at.y = __floats2half2_rn(atf.z, atf.w);

    uint2 sraw = *(const uint2*)&XL[(size_t)d * 128 + lane * 4];
    float m = score4_h2(sraw, xr, at);
    m += __shfl_xor_sync(FULL, m, 1);
    m += __shfl_xor_sync(FULL, m, 2);
    float den = 1.f;
    float4 acc = h4_to_f4(sraw);

    const int beg = g_off[d];
    const int cnt = g_off[d + 1] - beg;

    // batched edge indices: one coalesced LDG covers 32 edges, broadcast by shfl
    int b0 = 0, b1 = 0;
    if (cnt > 0)  b0 = __ldg(&g_ssrc[beg + (lane < cnt ? lane : cnt - 1)]);
    if (cnt > 32) b1 = __ldg(&g_ssrc[beg + (32 + lane < cnt ? 32 + lane : cnt - 1)]);

#define SRC1(j) ((j) < 32 ? __shfl_sync(FULL, b0, (j)) \
               : (j) < 64 ? __shfl_sync(FULL, b1, (j) - 32) \
               : __ldg(&g_ssrc[beg + (j)]))

    uint2 va, vb;
    if (cnt > 0) va = *(const uint2*)&XL[(size_t)SRC1(0) * 128 + lane * 4];
    if (cnt > 1) vb = *(const uint2*)&XL[(size_t)SRC1(1) * 128 + lane * 4];
    int j = 0;
    for (; j + 1 < cnt; j += 2) {
        uint2 r0 = va, r1 = vb;
        if (j + 2 < cnt) va = *(const uint2*)&XL[(size_t)SRC1(j + 2) * 128 + lane * 4];
        if (j + 3 < cnt) vb = *(const uint2*)&XL[(size_t)SRC1(j + 3) * 128 + lane * 4];
        float s0 = score4_h2(r0, xr, at);
        float s1 = score4_h2(r1, xr, at);
        s0 += __shfl_xor_sync(FULL, s0, 1);
        s1 += __shfl_xor_sync(FULL, s1, 1);
        s0 += __shfl_xor_sync(FULL, s0, 2);
        s1 += __shfl_xor_sync(FULL, s1, 2);
        float w0 = __expf(s0 - m), w1 = __expf(s1 - m);
        float4 c0 = h4_to_f4(r0), c1 = h4_to_f4(r1);
        den += w0 + w1;
        acc.x += w0 * c0.x + w1 * c1.x;
        acc.y += w0 * c0.y + w1 * c1.y;
        acc.z += w0 * c0.z + w1 * c1.z;
        acc.w += w0 * c0.w + w1 * c1.w;
    }
    if (j < cnt) {
        uint2 r0 = va;
        float s0 = score4_h2(r0, xr, at);
        s0 += __shfl_xor_sync(FULL, s0, 1);
        s0 += __shfl_xor_sync(FULL, s0, 2);
        float w0 = __expf(s0 - m);
        float4 c0 = h4_to_f4(r0);
        den += w0;
        acc.x += w0 * c0.x;
        acc.y += w0 * c0.y;
        acc.z += w0 * c0.z;
        acc.w += w0 * c0.w;
    }
#undef SRC1
    float inv = 1.f / den;
    float4 bi = *(const float4*)&bias[lane * 4];
    float o[4];
    o[0] = acc.x * inv + bi.x; o[1] = acc.y * inv + bi.y;
    o[2] = acc.z * inv + bi.z; o[3] = acc.w * inv + bi.w;
#pragma unroll
    for (int i = 0; i < 4; i++) o[i] = o[i] > 0.f ? o[i] : expm1f(o[i]);
    uint2 hv;
    *(__half2*)&hv.x = __floats2half2_rn(o[0], o[1]);
    *(__half2*)&hv.y = __floats2half2_rn(o[2], o[3]);
    *(uint2*)&g_h16[(size_t)d * 128 + lane * 4] = hv;
}

// ---------------- layer 2 attention: 16 lanes/node, shuffle-broadcast indices -----------
__global__ void k_attn2(const float* __restrict__ att2, const float* __restrict__ bias2,
                        float* __restrict__ dout, int N) {
    const int lane = threadIdx.x & 31;
    const int wid = threadIdx.x >> 5;
    const int grp = lane >> 4, gl = lane & 15;
    const int node = blockIdx.x * 16 + wid * 2 + grp;
    const unsigned mask = 0xFFFFu << (grp * 16);
    if (node >= N) return;
    const int d = node;
    const __half* XL = g_xl2h;

    uint2 xr = *(const uint2*)&g_xr2h[(size_t)d * 64 + gl * 4];
    float4 atf = *(const float4*)&att2[gl * 4];
    uint2 at;
    *(__half2*)&at.x = __floats2half2_rn(atf.x, atf.y);
    *(__half2*)&at.y = __floats2half2_rn(atf.z, atf.w);

    uint2 sraw = *(const uint2*)&XL[(size_t)d * 64 + gl * 4];
    float m = score4_h2(sraw, xr, at);
    m += __shfl_xor_sync(mask, m, 1);
    m += __shfl_xor_sync(mask, m, 2);
    m += __shfl_xor_sync(mask, m, 4);
    m += __shfl_xor_sync(mask, m, 8);
    float den = 1.f;
    float4 acc = h4_to_f4(sraw);

    const int beg = g_off[d];
    const int cnt = g_off[d + 1] - beg;

    int b0 = 0, b1 = 0;
    if (cnt > 0)  b0 = __ldg(&g_ssrc[beg + (gl < cnt ? gl : cnt - 1)]);
    if (cnt > 16) b1 = __ldg(&g_ssrc[beg + (16 + gl < cnt ? 16 + gl : cnt - 1)]);

#define SRC2(j) ((j) < 16 ? __shfl_sync(mask, b0, grp * 16 + (j)) \
               : (j) < 32 ? __shfl_sync(mask, b1, grp * 16 + (j) - 16) \
               : __ldg(&g_ssrc[beg + (j)]))

    uint2 va, vb;
    if (cnt > 0) va = *(const uint2*)&XL[(size_t)SRC2(0) * 64 + gl * 4];
    if (cnt > 1) vb = *(const uint2*)&XL[(size_t)SRC2(1) * 64 + gl * 4];
    int j = 0;
    for (; j + 1 < cnt; j += 2) {
        uint2 r0 = va, r1 = vb;
        if (j + 2 < cnt) va = *(const uint2*)&XL[(size_t)SRC2(j + 2) * 64 + gl * 4];
        if (j + 3 < cnt) vb = *(const uint2*)&XL[(size_t)SRC2(j + 3) * 64 + gl * 4];
        float s0 = score4_h2(r0, xr, at);
        float s1 = score4_h2(r1, xr, at);
#pragma unroll
        for (int o = 1; o <= 8; o <<= 1) {
            s0 += __shfl_xor_sync(mask, s0, o);
            s1 += __shfl_xor_sync(mask, s1, o);
        }
        float w0 = __expf(s0 - m), w1 = __expf(s1 - m);
        float4 c0 = h4_to_f4(r0), c1 = h4_to_f4(r1);
        den += w0 + w1;
        acc.x += w0 * c0.x + w1 * c1.x;
        acc.y += w0 * c0.y + w1 * c1.y;
        acc.z += w0 * c0.z + w1 * c1.z;
        acc.w += w0 * c0.w + w1 * c1.w;
    }
    if (j < cnt) {
        uint2 r0 = va;
        float s0 = score4_h2(r0, xr, at);
#pragma unroll
        for (int o = 1; o <= 8; o <<= 1) s0 += __shfl_xor_sync(mask, s0, o);
        float w0 = __expf(s0 - m);
        float4 c0 = h4_to_f4(r0);
        den += w0;
        acc.x += w0 * c0.x;
        acc.y += w0 * c0.y;
        acc.z += w0 * c0.z;
        acc.w += w0 * c0.w;
    }
#undef SRC2
    float inv = 1.f / den;
    float4 bi = *(const float4*)&bias2[gl * 4];
    float4 o;
    o.x = acc.x * inv + bi.x; o.y = acc.y * inv + bi.y;
    o.z = acc.z * inv + bi.z; o.w = acc.w * inv + bi.w;
    *(float4*)&dout[(size_t)d * 64 + gl * 4] = o;
}

// ---------------- launch ----------------
static inline int cdiv(long long a, int b) { return (int)((a + b - 1) / b); }

extern "C" void kernel_launch(void* const* d_in, const int* in_sizes, int n_in,
                              void* d_out, int out_size) {
    const float* x    = (const float*)d_in[0];
    const int*   ei   = (const int*)d_in[1];
    const float* Wl1  = (const float*)d_in[2];
    const float* bl1  = (const float*)d_in[3];
    const float* Wr1  = (const float*)d_in[4];
    const float* br1  = (const float*)d_in[5];
    const float* att1 = (const float*)d_in[6];
    const float* bias1= (const float*)d_in[7];
    const float* Wl2  = (const float*)d_in[8];
    const float* bl2  = (const float*)d_in[9];
    const float* Wr2  = (const float*)d_in[10];
    const float* br2  = (const float*)d_in[11];
    const float* att2 = (const float*)d_in[12];
    const float* bias2= (const float*)d_in[13];
    float* dout = (float*)d_out;

    const int N = in_sizes[0] / 128;
    const int E = in_sizes[1] / 2;
    const int NB = cdiv(N, SCAN_B);

    __half *xl1h, *xr1h, *xl2h, *xr2h, *x16, *h16;
    cudaGetSymbolAddress((void**)&xl1h, g_xl1h);
    cudaGetSymbolAddress((void**)&xr1h, g_xr1h);
    cudaGetSymbolAddress((void**)&xl2h, g_xl2h);
    cudaGetSymbolAddress((void**)&xr2h, g_xr2h);
    cudaGetSymbolAddress((void**)&x16,  g_x16);
    cudaGetSymbolAddress((void**)&h16,  g_h16);
    __half *w1l16, *w1r16, *w2l16, *w2r16;
    cudaGetSymbolAddress((void**)&w1l16, g_w1l16);
    cudaGetSymbolAddress((void**)&w1r16, g_w1r16);
    cudaGetSymbolAddress((void**)&w2l16, g_w2l16);
    cudaGetSymbolAddress((void**)&w2r16, g_w2r16);

    const int smemT = 128 * 136 * 2 + 2 * (64 * 136 * 2);   // 34816 + 34816 = 69632
    cudaFuncSetAttribute((k_gemm_mma<128, 64>), cudaFuncAttributeMaxDynamicSharedMemorySize, smemT);
    cudaFuncSetAttribute((k_gemm_mma<64, 64>),  cudaFuncAttributeMaxDynamicSharedMemorySize, smemT);

    static cudaStream_t s1 = nullptr;
    static cudaEvent_t evFork = nullptr, evJoin = nullptr;
    if (!s1) {
        cudaStreamCreateWithFlags(&s1, cudaStreamNonBlocking);
        cudaEventCreateWithFlags(&evFork, cudaEventDisableTiming);
        cudaEventCreateWithFlags(&evJoin, cudaEventDisableTiming);
    }

    // fork side stream
    cudaEventRecord(evFork, 0);
    cudaStreamWaitEvent(s1, evFork, 0);

    // submission order: k_gemm_mma<128,64> is the 4th launch (ncu profiles #4)
    k_wprep<<<cdiv(49152, 256), 256, 0, s1>>>(Wl1, Wr1, Wl2, Wr2);             // 1
    k_xprep<<<cdiv((long long)N * 32, 256), 256, 0, s1>>>(x, N * 32);          // 2
    k_init <<<cdiv(N, 256), 256>>>(ei, E, N);                                   // 3
    k_gemm_mma<128, 64><<<dim3(cdiv(N, 128), 2), 256, smemT, s1>>>(
        x16, w1l16, w1r16, bl1, br1, xl1h, xr1h, N);                            // 4
    cudaEventRecord(evJoin, s1);

    k_hist   <<<cdiv(E, 256), 256>>>(ei, E);                                    // 5
    k_scan1  <<<NB, SCAN_B>>>(N);                                               // 6
    k_scan2  <<<1, 128>>>(NB, N);                                               // 7
    k_scan3  <<<cdiv(N, 256), 256>>>(N);                                        // 8
    k_scatter<<<cdiv(E, 256), 256>>>(ei, E);                                    // 9

    // join: attn1 needs CSR + GEMM1
    cudaStreamWaitEvent(0, evJoin, 0);

    k_attn1<<<cdiv(N, 8), 256>>>(att1, bias1, N);                               // 10
    k_gemm_mma<64, 64><<<dim3(cdiv(N, 128), 1), 256, smemT>>>(
        h16, w2l16, w2r16, bl2, br2, xl2h, xr2h, N);                            // 11
    k_attn2<<<cdiv(N, 16), 256>>>(att2, bias2, dout, N);                        // 12
}

// round 17
// speedup vs baseline: 1.0818x; 1.0818x over previous
#include <cuda_runtime.h>
#include <cuda_fp16.h>
#include <cstdint>

#define NN_CAP 100000
#define EE_CAP 1600000
#define SCAN_B 1024

// ---------------- scratch (device globals) ----------------
__device__ int    g_is64;
__device__ int    g_cnt[NN_CAP];
__device__ int    g_off[NN_CAP + 1];
__device__ int    g_cur[NN_CAP];
__device__ int    g_bsum[(NN_CAP + SCAN_B - 1) / SCAN_B];
__device__ int    g_bpre[(NN_CAP + SCAN_B - 1) / SCAN_B];
__device__ int    g_ssrc[EE_CAP];
__device__ __half g_xl1h[(size_t)NN_CAP * 128];
__device__ __half g_xr1h[(size_t)NN_CAP * 128];
__device__ __half g_xl2h[(size_t)NN_CAP * 64];
__device__ __half g_xr2h[(size_t)NN_CAP * 64];
__device__ __half g_x16[(size_t)NN_CAP * 128];
__device__ __half g_h16[(size_t)NN_CAP * 128];
__device__ __half g_w1l16[16384], g_w1r16[16384];
__device__ __half g_w2l16[8192],  g_w2r16[8192];

// ---------------- helpers ----------------
__device__ __forceinline__ uint32_t smem_u32(const void* p) {
    uint32_t a;
    asm("{ .reg .u64 t; cvta.to.shared.u64 t, %1; cvt.u32.u64 %0, t; }" : "=r"(a) : "l"(p));
    return a;
}
__device__ __forceinline__ void ldsm_x4(uint32_t& r0, uint32_t& r1, uint32_t& r2, uint32_t& r3,
                                        uint32_t addr) {
    asm volatile("ldmatrix.sync.aligned.m8n8.x4.shared.b16 {%0,%1,%2,%3}, [%4];"
                 : "=r"(r0), "=r"(r1), "=r"(r2), "=r"(r3) : "r"(addr));
}
__device__ __forceinline__ void mma16816f(float* c, const uint32_t* a, const uint32_t* b) {
    asm volatile(
        "mma.sync.aligned.m16n8k16.row.col.f32.f16.f16.f32 "
        "{%0,%1,%2,%3}, {%4,%5,%6,%7}, {%8,%9}, {%0,%1,%2,%3};"
        : "+f"(c[0]), "+f"(c[1]), "+f"(c[2]), "+f"(c[3])
        : "r"(a[0]), "r"(a[1]), "r"(a[2]), "r"(a[3]), "r"(b[0]), "r"(b[1]));
}
__device__ __forceinline__ float4 h4_to_f4(uint2 u) {
    float2 a = __half22float2(*(__half2*)&u.x);
    float2 b = __half22float2(*(__half2*)&u.y);
    return make_float4(a.x, a.y, b.x, b.y);
}
__device__ __forceinline__ float score4_h2(uint2 xl, uint2 xr, uint2 at) {
    const __half2 k = __float2half2_rn(0.2f);
    __half2 e0 = __hadd2(*(__half2*)&xl.x, *(__half2*)&xr.x);
    __half2 e1 = __hadd2(*(__half2*)&xl.y, *(__half2*)&xr.y);
    __half2 l0 = __hmax2(e0, __hmul2(e0, k));
    __half2 l1 = __hmax2(e1, __hmul2(e1, k));
    __half2 p  = __hmul2(l0, *(__half2*)&at.x);
    p = __hfma2(l1, *(__half2*)&at.y, p);
    float2 f = __half22float2(p);
    return f.x + f.y;
}
__device__ __forceinline__ int edge_dst(const int* __restrict__ ei, int e, int E, int is64) {
    return is64 ? ei[2 * (E + e)] : ei[E + e];
}
__device__ __forceinline__ int edge_src(const int* __restrict__ ei, int e, int E, int is64) {
    return is64 ? ei[2 * e] : ei[e];
}

// ---------------- init: zero counts + dtype detect (block 0) ----------------
__global__ void k_init(const int* __restrict__ ei, int E, int N) {
    int t = blockIdx.x * blockDim.x + threadIdx.x;
    if (t < N) g_cnt[t] = 0;
    if (blockIdx.x == 0) {
        __shared__ int nz;
        if (threadIdx.x == 0) nz = 0;
        __syncthreads();
        int cnt = E < 4096 ? E : 4096;
        for (int i = threadIdx.x; i < cnt; i += blockDim.x)
            if (ei[2 * i + 1] != 0) nz = 1;
        __syncthreads();
        if (threadIdx.x == 0) g_is64 = (nz == 0) ? 1 : 0;
    }
}

// ---------------- CSR build ----------------
__global__ void k_hist(const int* __restrict__ ei, int E) {
    int e = blockIdx.x * blockDim.x + threadIdx.x;
    if (e >= E) return;
    atomicAdd(&g_cnt[edge_dst(ei, e, E, g_is64)], 1);
}
__global__ void k_scan1(int N) {
    __shared__ int wsum[32];
    const int tid = threadIdx.x;
    const int i = blockIdx.x * SCAN_B + tid;
    const int lane = tid & 31, wid = tid >> 5;
    int v = (i < N) ? g_cnt[i] : 0;
    int incl = v;
#pragma unroll
    for (int o = 1; o < 32; o <<= 1) {
        int t = __shfl_up_sync(0xFFFFFFFFu, incl, o);
        if (lane >= o) incl += t;
    }
    if (lane == 31) wsum[wid] = incl;
    __syncthreads();
    if (wid == 0) {
        int w = wsum[lane];
        int wi = w;
#pragma unroll
        for (int o = 1; o < 32; o <<= 1) {
            int t = __shfl_up_sync(0xFFFFFFFFu, wi, o);
            if (lane >= o) wi += t;
        }
        wsum[lane] = wi - w;
        if (lane == 31) g_bsum[blockIdx.x] = wi;
    }
    __syncthreads();
    if (i < N) g_off[i] = incl - v + wsum[wid];
}
__global__ void k_scan2(int NB, int N) {
    const int lane = threadIdx.x & 31, wid = threadIdx.x >> 5;
    __shared__ int wsum[4];
    int v = (threadIdx.x < NB) ? g_bsum[threadIdx.x] : 0;
    int incl = v;
#pragma unroll
    for (int o = 1; o < 32; o <<= 1) {
        int t = __shfl_up_sync(0xFFFFFFFFu, incl, o);
        if (lane >= o) incl += t;
    }
    if (lane == 31) wsum[wid] = incl;
    __syncthreads();
    int pre = 0;
    for (int w = 0; w < wid; w++) pre += wsum[w];
    if (threadIdx.x < NB) g_bpre[threadIdx.x] = pre + incl - v;
    if (threadIdx.x == 127) g_off[N] = pre + incl;
}
__global__ void k_scan3(int N) {
    int t = blockIdx.x * blockDim.x + threadIdx.x;
    if (t >= N) return;
    int o = g_off[t] + g_bpre[t >> 10];
    g_off[t] = o;
    g_cur[t] = o;
}
__global__ void k_scatter(const int* __restrict__ ei, int E) {
    int e = blockIdx.x * blockDim.x + threadIdx.x;
    if (e >= E) return;
    int is64 = g_is64;
    int s = edge_src(ei, e, E, is64), d = edge_dst(ei, e, E, is64);
    int pos = atomicAdd(&g_cur[d], 1);
    g_ssrc[pos] = s;
}

// ---------------- weight prep: transpose to [NOUT][128] fp16 ----------------
__global__ void k_wprep(const float* __restrict__ W1l, const float* __restrict__ W1r,
                        const float* __restrict__ W2l, const float* __restrict__ W2r) {
    int t = blockIdx.x * blockDim.x + threadIdx.x;
    const float* W; __half* o; int NOUT, idx;
    if      (t < 16384)  { W = W1l; o = g_w1l16; NOUT = 128; idx = t; }
    else if (t < 32768)  { W = W1r; o = g_w1r16; NOUT = 128; idx = t - 16384; }
    else if (t < 40960)  { W = W2l; o = g_w2l16; NOUT = 64;  idx = t - 32768; }
    else if (t < 49152)  { W = W2r; o = g_w2r16; NOUT = 64;  idx = t - 40960; }
    else return;
    int n = idx >> 7, k = idx & 127;
    o[idx] = __float2half_rn(W[k * NOUT + n]);
}

// ---------------- X prep: fp32 -> fp16 ----------------
__global__ void k_xprep(const float* __restrict__ X, int total4) {
    int t = blockIdx.x * blockDim.x + threadIdx.x;
    if (t >= total4) return;
    float4 v = *(const float4*)&X[t * 4];
    uint2 h;
    *(__half2*)&h.x = __floats2half2_rn(v.x, v.y);
    *(__half2*)&h.y = __floats2half2_rn(v.z, v.w);
    *(uint2*)&g_x16[t * 4] = h;
}

// ---------------- single-pass fp16 mma.sync GEMM pair (NTILE=32, 3 CTAs/SM) ----------
template <int NOUT, int NTILE>
__global__ void __launch_bounds__(256, 3) k_gemm_mma(
    const __half* __restrict__ Xh,
    const __half* __restrict__ Wl, const __half* __restrict__ Wr,
    const float* __restrict__ bl, const float* __restrict__ br,
    __half* __restrict__ Ylh, __half* __restrict__ Yrh, int nrows)
{
    constexpr int PITCH = 136;
    constexpr int ABYTES = 128 * PITCH * 2;
    constexpr int BBYTES = NTILE * PITCH * 2;
    constexpr int WN = NTILE / 2;
    constexpr int NFRAG = WN / 8;

    extern __shared__ char sm[];
    __half* At = (__half*)sm;
    __half* Bt = (__half*)(sm + ABYTES);

    const int tid = threadIdx.x, wid = tid >> 5, lane = tid & 31;
    const int wm = wid & 3, wn = wid >> 2;
    const int base = blockIdx.x * 128;
    const int cbase = blockIdx.y * NTILE;

    for (int c = tid; c < 2048; c += 256) {
        int row = c >> 4, col8 = (c & 15) << 3;
        int gr = base + row;
        uint4 v = make_uint4(0u, 0u, 0u, 0u);
        if (gr < nrows) v = *(const uint4*)&Xh[(size_t)gr * 128 + col8];
        *(uint4*)&At[row * PITCH + col8] = v;
    }
    const __half* wsrc[2] = {Wl, Wr};
#pragma unroll
    for (int w = 0; w < 2; w++) {
        __half* dst = Bt + w * (NTILE * PITCH);
        const __half* src = wsrc[w] + (size_t)cbase * 128;
        for (int c = tid; c < NTILE * 16; c += 256) {
            int row = c >> 4, col8 = (c & 15) << 3;
            *(uint4*)&dst[row * PITCH + col8] = *(const uint4*)&src[row * 128 + col8];
        }
    }
    __syncthreads();

    const int quad = lane >> 3, r = lane & 7;
    const int a_row_off = (quad & 1) * 8 + r, a_col_off = (quad >> 1) * 8;
    const int b_row_off = (quad >> 1) * 8 + r, b_col_off = (quad & 1) * 8;

    const uint32_t a_u = smem_u32(At), b_u = smem_u32(Bt);

    float acc[2][2][NFRAG][4];
#pragma unroll
    for (int o = 0; o < 2; o++)
#pragma unroll
        for (int mf = 0; mf < 2; mf++)
#pragma unroll
            for (int nf = 0; nf < NFRAG; nf++)
                acc[o][mf][nf][0] = acc[o][mf][nf][1] = acc[o][mf][nf][2] = acc[o][mf][nf][3] = 0.f;

#pragma unroll
    for (int ks = 0; ks < 8; ks++) {
        uint32_t af[2][4];
#pragma unroll
        for (int mf = 0; mf < 2; mf++) {
            uint32_t off = ((wm * 32 + mf * 16 + a_row_off) * PITCH + ks * 16 + a_col_off) * 2;
            ldsm_x4(af[mf][0], af[mf][1], af[mf][2], af[mf][3], a_u + off);
        }
        uint32_t boff = ((wn * WN + b_row_off) * PITCH + ks * 16 + b_col_off) * 2;
        uint32_t bf[2][NFRAG][2];
#pragma unroll
        for (int out = 0; out < 2; out++) {
            uint32_t d0, d1, d2, d3;
            ldsm_x4(d0, d1, d2, d3, b_u + (uint32_t)out * BBYTES + boff);
            bf[out][0][0] = d0; bf[out][0][1] = d1;
            bf[out][1][0] = d2; bf[out][1][1] = d3;
        }
#pragma unroll
        for (int out = 0; out < 2; out++)
#pragma unroll
            for (int mf = 0; mf < 2; mf++)
#pragma unroll
                for (int nf = 0; nf < NFRAG; nf++)
                    mma16816f(acc[out][mf][nf], af[mf], bf[out][nf]);
    }

#pragma unroll
    for (int out = 0; out < 2; out++) {
        const float* bias = out ? br : bl;
        __half* Y = out ? Yrh : Ylh;
#pragma unroll
        for (int mf = 0; mf < 2; mf++) {
            int row0 = base + wm * 32 + mf * 16 + (lane >> 2);
#pragma unroll
            for (int nf = 0; nf < NFRAG; nf++) {
                int col = cbase + wn * WN + nf * 8 + (lane & 3) * 2;
                float b0 = __ldg(&bias[col]), b1 = __ldg(&bias[col + 1]);
                if (row0 < nrows)
                    *(__half2*)&Y[(size_t)row0 * NOUT + col] =
                        __floats2half2_rn(acc[out][mf][nf][0] + b0, acc[out][mf][nf][1] + b1);
                if (row0 + 8 < nrows)
                    *(__half2*)&Y[(size_t)(row0 + 8) * NOUT + col] =
                        __floats2half2_rn(acc[out][mf][nf][2] + b0, acc[out][mf][nf][3] + b1);
            }
        }
    }
}

// ---------------- layer 1 attention: 4-deep prefetch, 2-edge compute ----------
__global__ void k_attn1(const float* __restrict__ att, const float* __restrict__ bias, int N) {
    int node = blockIdx.x * 8 + (threadIdx.x >> 5);
    int lane = threadIdx.x & 31;
    if (node >= N) return;
    const int d = node;
    const __half* XL = g_xl1h;
    const unsigned FULL = 0xFFFFFFFFu;

    uint2 xr = *(const uint2*)&g_xr1h[(size_t)d * 128 + lane * 4];
    float4 atf = *(const float4*)&att[lane * 4];
    uint2 at;
    *(__half2*)&at.x = __floats2half2_rn(atf.x, atf.y);
    *(__half2*)&at.y = __floats2half2_rn(atf.z, atf.w);

    uint2 sraw = *(const uint2*)&XL[(size_t)d * 128 + lane * 4];
    float m = score4_h2(sraw, xr, at);
    m += __shfl_xor_sync(FULL, m, 1);
    m += __shfl_xor_sync(FULL, m, 2);
    float den = 1.f;
    float4 acc = h4_to_f4(sraw);

    const int beg = g_off[d];
    const int cnt = g_off[d + 1] - beg;
    uint2 va, vb, vc, vd;
    if (cnt > 0) { int s = __ldg(&g_ssrc[beg]);     va = *(const uint2*)&XL[(size_t)s * 128 + lane * 4]; }
    if (cnt > 1) { int s = __ldg(&g_ssrc[beg + 1]); vb = *(const uint2*)&XL[(size_t)s * 128 + lane * 4]; }
    if (cnt > 2) { int s = __ldg(&g_ssrc[beg + 2]); vc = *(const uint2*)&XL[(size_t)s * 128 + lane * 4]; }
    if (cnt > 3) { int s = __ldg(&g_ssrc[beg + 3]); vd = *(const uint2*)&XL[(size_t)s * 128 + lane * 4]; }
    int j = 0;
    for (; j + 1 < cnt; j += 2) {
        uint2 r0 = va, r1 = vb;
        va = vc; vb = vd;
        if (j + 4 < cnt) { int s = __ldg(&g_ssrc[beg + j + 4]); vc = *(const uint2*)&XL[(size_t)s * 128 + lane * 4]; }
        if (j + 5 < cnt) { int s = __ldg(&g_ssrc[beg + j + 5]); vd = *(const uint2*)&XL[(size_t)s * 128 + lane * 4]; }
        float s0 = score4_h2(r0, xr, at);
        float s1 = score4_h2(r1, xr, at);
        s0 += __shfl_xor_sync(FULL, s0, 1);
        s1 += __shfl_xor_sync(FULL, s1, 1);
        s0 += __shfl_xor_sync(FULL, s0, 2);
        s1 += __shfl_xor_sync(FULL, s1, 2);
        float w0 = __expf(s0 - m), w1 = __expf(s1 - m);
        float4 c0 = h4_to_f4(r0), c1 = h4_to_f4(r1);
        den += w0 + w1;
        acc.x += w0 * c0.x + w1 * c1.x;
        acc.y += w0 * c0.y + w1 * c1.y;
        acc.z += w0 * c0.z + w1 * c1.z;
        acc.w += w0 * c0.w + w1 * c1.w;
    }
    if (j < cnt) {
        uint2 r0 = va;
        float s0 = score4_h2(r0, xr, at);
        s0 += __shfl_xor_sync(FULL, s0, 1);
        s0 += __shfl_xor_sync(FULL, s0, 2);
        float w0 = __expf(s0 - m);
        float4 c0 = h4_to_f4(r0);
        den += w0;
        acc.x += w0 * c0.x;
        acc.y += w0 * c0.y;
        acc.z += w0 * c0.z;
        acc.w += w0 * c0.w;
    }
    float inv = 1.f / den;
    float4 bi = *(const float4*)&bias[lane * 4];
    float o[4];
    o[0] = acc.x * inv + bi.x; o[1] = acc.y * inv + bi.y;
    o[2] = acc.z * inv + bi.z; o[3] = acc.w * inv + bi.w;
#pragma unroll
    for (int i = 0; i < 4; i++) o[i] = o[i] > 0.f ? o[i] : expm1f(o[i]);
    uint2 hv;
    *(__half2*)&hv.x = __floats2half2_rn(o[0], o[1]);
    *(__half2*)&hv.y = __floats2half2_rn(o[2], o[3]);
    *(uint2*)&g_h16[(size_t)d * 128 + lane * 4] = hv;
}

// ---------------- layer 2 attention: 16 lanes/node, 4-deep prefetch ----------------
__global__ void k_attn2(const float* __restrict__ att2, const float* __restrict__ bias2,
                        float* __restrict__ dout, int N) {
    const int lane = threadIdx.x & 31;
    const int wid = threadIdx.x >> 5;
    const int grp = lane >> 4, gl = lane & 15;
    const int node = blockIdx.x * 16 + wid * 2 + grp;
    const unsigned mask = 0xFFFFu << (grp * 16);
    if (node >= N) return;
    const int d = node;
    const __half* XL = g_xl2h;

    uint2 xr = *(const uint2*)&g_xr2h[(size_t)d * 64 + gl * 4];
    float4 atf = *(const float4*)&att2[gl * 4];
    uint2 at;
    *(__half2*)&at.x = __floats2half2_rn(atf.x, atf.y);
    *(__half2*)&at.y = __floats2half2_rn(atf.z, atf.w);

    uint2 sraw = *(const uint2*)&XL[(size_t)d * 64 + gl * 4];
    float m = score4_h2(sraw, xr, at);
    m += __shfl_xor_sync(mask, m, 1);
    m += __shfl_xor_sync(mask, m, 2);
    m += __shfl_xor_sync(mask, m, 4);
    m += __shfl_xor_sync(mask, m, 8);
    float den = 1.f;
    float4 acc = h4_to_f4(sraw);

    const int beg = g_off[d];
    const int cnt = g_off[d + 1] - beg;
    uint2 va, vb, vc, vd;
    if (cnt > 0) { int s = __ldg(&g_ssrc[beg]);     va = *(const uint2*)&XL[(size_t)s * 64 + gl * 4]; }
    if (cnt > 1) { int s = __ldg(&g_ssrc[beg + 1]); vb = *(const uint2*)&XL[(size_t)s * 64 + gl * 4]; }
    if (cnt > 2) { int s = __ldg(&g_ssrc[beg + 2]); vc = *(const uint2*)&XL[(size_t)s * 64 + gl * 4]; }
    if (cnt > 3) { int s = __ldg(&g_ssrc[beg + 3]); vd = *(const uint2*)&XL[(size_t)s * 64 + gl * 4]; }
    int j = 0;
    for (; j + 1 < cnt; j += 2) {
        uint2 r0 = va, r1 = vb;
        va = vc; vb = vd;
        if (j + 4 < cnt) { int s = __ldg(&g_ssrc[beg + j + 4]); vc = *(const uint2*)&XL[(size_t)s * 64 + gl * 4]; }
        if (j + 5 < cnt) { int s = __ldg(&g_ssrc[beg + j + 5]); vd = *(const uint2*)&XL[(size_t)s * 64 + gl * 4]; }
        float s0 = score4_h2(r0, xr, at);
        float s1 = score4_h2(r1, xr, at);
#pragma unroll
        for (int o = 1; o <= 8; o <<= 1) {
            s0 += __shfl_xor_sync(mask, s0, o);
            s1 += __shfl_xor_sync(mask, s1, o);
        }
        float w0 = __expf(s0 - m), w1 = __expf(s1 - m);
        float4 c0 = h4_to_f4(r0), c1 = h4_to_f4(r1);
        den += w0 + w1;
        acc.x += w0 * c0.x + w1 * c1.x;
        acc.y += w0 * c0.y + w1 * c1.y;
        acc.z += w0 * c0.z + w1 * c1.z;
        acc.w += w0 * c0.w + w1 * c1.w;
    }
    if (j < cnt) {
        uint2 r0 = va;
        float s0 = score4_h2(r0, xr, at);
#pragma unroll
        for (int o = 1; o <= 8; o <<= 1) s0 += __shfl_xor_sync(mask, s0, o);
        float w0 = __expf(s0 - m);
        float4 c0 = h4_to_f4(r0);
        den += w0;
        acc.x += w0 * c0.x;
        acc.y += w0 * c0.y;
        acc.z += w0 * c0.z;
        acc.w += w0 * c0.w;
    }
    float inv = 1.f / den;
    float4 bi = *(const float4*)&bias2[gl * 4];
    float4 o;
    o.x = acc.x * inv + bi.x; o.y = acc.y * inv + bi.y;
    o.z = acc.z * inv + bi.z; o.w = acc.w * inv + bi.w;
    *(float4*)&dout[(size_t)d * 64 + gl * 4] = o;
}

// ---------------- launch ----------------
static inline int cdiv(long long a, int b) { return (int)((a + b - 1) / b); }

extern "C" void kernel_launch(void* const* d_in, const int* in_sizes, int n_in,
                              void* d_out, int out_size) {
    const float* x    = (const float*)d_in[0];
    const int*   ei   = (const int*)d_in[1];
    const float* Wl1  = (const float*)d_in[2];
    const float* bl1  = (const float*)d_in[3];
    const float* Wr1  = (const float*)d_in[4];
    const float* br1  = (const float*)d_in[5];
    const float* att1 = (const float*)d_in[6];
    const float* bias1= (const float*)d_in[7];
    const float* Wl2  = (const float*)d_in[8];
    const float* bl2  = (const float*)d_in[9];
    const float* Wr2  = (const float*)d_in[10];
    const float* br2  = (const float*)d_in[11];
    const float* att2 = (const float*)d_in[12];
    const float* bias2= (const float*)d_in[13];
    float* dout = (float*)d_out;

    const int N = in_sizes[0] / 128;
    const int E = in_sizes[1] / 2;
    const int NB = cdiv(N, SCAN_B);

    __half *xl1h, *xr1h, *xl2h, *xr2h, *x16, *h16;
    cudaGetSymbolAddress((void**)&xl1h, g_xl1h);
    cudaGetSymbolAddress((void**)&xr1h, g_xr1h);
    cudaGetSymbolAddress((void**)&xl2h, g_xl2h);
    cudaGetSymbolAddress((void**)&xr2h, g_xr2h);
    cudaGetSymbolAddress((void**)&x16,  g_x16);
    cudaGetSymbolAddress((void**)&h16,  g_h16);
    __half *w1l16, *w1r16, *w2l16, *w2r16;
    cudaGetSymbolAddress((void**)&w1l16, g_w1l16);
    cudaGetSymbolAddress((void**)&w1r16, g_w1r16);
    cudaGetSymbolAddress((void**)&w2l16, g_w2l16);
    cudaGetSymbolAddress((void**)&w2r16, g_w2r16);

    const int smemT = 128 * 136 * 2 + 2 * (32 * 136 * 2);   // 52224 -> 3 CTAs/SM
    cudaFuncSetAttribute((k_gemm_mma<128, 32>), cudaFuncAttributeMaxDynamicSharedMemorySize, smemT);
    cudaFuncSetAttribute((k_gemm_mma<64, 32>),  cudaFuncAttributeMaxDynamicSharedMemorySize, smemT);

    static cudaStream_t s1 = nullptr;
    static cudaEvent_t evFork = nullptr, evJoin = nullptr;
    if (!s1) {
        cudaStreamCreateWithFlags(&s1, cudaStreamNonBlocking);
        cudaEventCreateWithFlags(&evFork, cudaEventDisableTiming);
        cudaEventCreateWithFlags(&evJoin, cudaEventDisableTiming);
    }

    // fork side stream
    cudaEventRecord(evFork, 0);
    cudaStreamWaitEvent(s1, evFork, 0);

    // submission order: k_gemm_mma<128,32> is the 4th launch (ncu profiles #4)
    k_wprep<<<cdiv(49152, 256), 256, 0, s1>>>(Wl1, Wr1, Wl2, Wr2);             // 1
    k_xprep<<<cdiv((long long)N * 32, 256), 256, 0, s1>>>(x, N * 32);          // 2
    k_init <<<cdiv(N, 256), 256>>>(ei, E, N);                                   // 3
    k_gemm_mma<128, 32><<<dim3(cdiv(N, 128), 4), 256, smemT, s1>>>(
        x16, w1l16, w1r16, bl1, br1, xl1h, xr1h, N);                            // 4
    cudaEventRecord(evJoin, s1);

    k_hist   <<<cdiv(E, 256), 256>>>(ei, E);                                    // 5
    k_scan1  <<<NB, SCAN_B>>>(N);                                               // 6
    k_scan2  <<<1, 128>>>(NB, N);                                               // 7
    k_scan3  <<<cdiv(N, 256), 256>>>(N);                                        // 8
    k_scatter<<<cdiv(E, 256), 256>>>(ei, E);                                    // 9

    // join: attn1 needs CSR + GEMM1
    cudaStreamWaitEvent(0, evJoin, 0);

    k_attn1<<<cdiv(N, 8), 256>>>(att1, bias1, N);                               // 10
    k_gemm_mma<64, 32><<<dim3(cdiv(N, 128), 2), 256, smemT>>>(
        h16, w2l16, w2r16, bl2, br2, xl2h, xr2h, N);                            // 11
    k_attn2<<<cdiv(N, 16), 256>>>(att2, bias2, dout, N);                        // 12
}